// round 2
// baseline (speedup 1.0000x reference)
#include <cuda_runtime.h>
#include <math.h>
#include <stdint.h>

// Problem constants
// S=64 sentences, W=128 words, D=256 emb, HW=256 word hidden, HS=512 sent hidden, C=13

// ---------------------------------------------------------------------------
// Scratch (static device globals — no allocation allowed)
// ---------------------------------------------------------------------------
__device__ float g_Gi[2u*128*64*768];   // [d][w][s][768]  gi = x@Wi^T + bi
__device__ float g_H[2u*129*64*256];    // [d][w][s][256]  h states, w=0 is h0=0
__device__ float g_Uw[64u*128*512];     // [s][w][512]     u_word
__device__ float g_sent[64*512];        // sent_summ
__device__ float g_sgi[2*64*1536];      // sentence gi
__device__ float g_sentenc[64*1024];
__device__ float g_usent[64*1024];
__device__ int   g_flag[2*8*129];       // [d][sg][w] producer counters

__device__ __forceinline__ float sigf(float x) { return 1.f / (1.f + expf(-x)); }

// ---------------------------------------------------------------------------
// K0: zero flags + h0, fill attention-weight outputs (exact ones)
// ---------------------------------------------------------------------------
__global__ void k0_init(float* __restrict__ out, int ones_n) {
    int i = blockIdx.x * blockDim.x + threadIdx.x;
    int stride = gridDim.x * blockDim.x;
    for (int j = i; j < 2 * 8 * 129; j += stride) g_flag[j] = 0;
    for (int j = i; j < 64 * 256; j += stride) {
        g_H[j] = 0.f;                      // d=0, w=0
        g_H[129u * 64 * 256 + j] = 0.f;    // d=1, w=0
    }
    for (int j = i; j < ones_n; j += stride) out[j] = 1.0f;
}

// ---------------------------------------------------------------------------
// Shared 64x64x16 fp32 GEMM micro-kernel (4x4 register tile per thread)
// ---------------------------------------------------------------------------
__device__ __forceinline__ void mm16(const float As[16][64], const float Bs[16][64],
                                     int tx, int ty, float acc[4][4]) {
#pragma unroll
    for (int k = 0; k < 16; ++k) {
        float4 a = *(const float4*)&As[k][ty * 4];
        float4 b = *(const float4*)&Bs[k][tx * 4];
        acc[0][0] += a.x * b.x; acc[0][1] += a.x * b.y; acc[0][2] += a.x * b.z; acc[0][3] += a.x * b.w;
        acc[1][0] += a.y * b.x; acc[1][1] += a.y * b.y; acc[1][2] += a.y * b.z; acc[1][3] += a.y * b.w;
        acc[2][0] += a.z * b.x; acc[2][1] += a.z * b.y; acc[2][2] += a.z * b.z; acc[2][3] += a.z * b.w;
        acc[3][0] += a.w * b.x; acc[3][1] += a.w * b.y; acc[3][2] += a.w * b.z; acc[3][3] += a.w * b.w;
    }
}

// ---------------------------------------------------------------------------
// K1: Gi[d][w][s][j] = emb[doc[s][w]] @ Wi[d]^T + bi[d]   (gather fused)
// grid (12, 128, 2), 256 thr. Row tile = fixed w, s = 0..63.
// ---------------------------------------------------------------------------
__global__ void __launch_bounds__(256) k1_gi(const int* __restrict__ doc,
                                             const float* __restrict__ emb,
                                             const float* __restrict__ Wi,
                                             const float* __restrict__ bi) {
    __shared__ float As[16][64];
    __shared__ float Bs[16][64];
    __shared__ int toks[64];
    const int d  = blockIdx.z;
    const int j0 = blockIdx.x * 64;
    const int w  = blockIdx.y;
    const int tid = threadIdx.x;
    if (tid < 64) toks[tid] = doc[tid * 128 + w];   // s = tid
    __syncthreads();
    const int tx = tid & 15, ty = tid >> 4;
    const int li = tid >> 2;
    const int lk = (tid & 3) << 2;
    const float* WiD = Wi + (size_t)d * 768 * 256;
    float acc[4][4] = {};
    for (int kt = 0; kt < 256; kt += 16) {
        float4 av = *(const float4*)(emb + (size_t)toks[li] * 256 + kt + lk);
        float4 bv = *(const float4*)(WiD + (size_t)(j0 + li) * 256 + kt + lk);
        As[lk + 0][li] = av.x; As[lk + 1][li] = av.y; As[lk + 2][li] = av.z; As[lk + 3][li] = av.w;
        Bs[lk + 0][li] = bv.x; Bs[lk + 1][li] = bv.y; Bs[lk + 2][li] = bv.z; Bs[lk + 3][li] = bv.w;
        __syncthreads();
        mm16(As, Bs, tx, ty, acc);
        __syncthreads();
    }
#pragma unroll
    for (int ii = 0; ii < 4; ++ii) {
        int r = w * 64 + ty * 4 + ii;
#pragma unroll
        for (int jj = 0; jj < 4; ++jj) {
            int j = j0 + tx * 4 + jj;
            g_Gi[((size_t)d * 8192 + r) * 768 + j] = acc[ii][jj] + bi[d * 768 + j];
        }
    }
}

// ---------------------------------------------------------------------------
// K2: word GRU recurrence. 128 blocks = dir(2) x ktile(8 x 32cols) x sgroup(8 x 8sent)
// Weight slice (96 x 256) cached in SMEM, h exchanged via L2 + per-group flags.
// ---------------------------------------------------------------------------
__global__ void __launch_bounds__(256) k2_rec(const float* __restrict__ Wh,
                                              const float* __restrict__ bh_g) {
    const int b  = blockIdx.x;
    const int d  = b >> 6;
    const int kt = (b >> 3) & 7;
    const int sg = b & 7;
    const int k0 = kt * 32;
    const int s0 = sg * 8;
    const int tid = threadIdx.x;
    const int kk  = tid & 31;
    const int q   = tid >> 5;     // 8 K-split chunks of 32
    const int sl2 = tid >> 5;     // final-phase sentence
    const int kk2 = tid & 31;     // final-phase column

    extern __shared__ float sm[];
    float* wsh  = sm;                    // 96 x 257 (padded)
    float* hbuf = wsh + 96 * 257;        // 8 x 256
    float* red  = hbuf + 8 * 256;        // 8 x 96 x 9 (padded)

    // Load this block's weight slice: rows {third*256 + k0 + kr} for third 0..2
    const float* WhD = Wh + (size_t)d * 768 * 256;
    for (int e = tid; e < 96 * 256; e += 256) {
        int rr = e >> 8, c = e & 255;
        int third = rr / 32, kr = rr % 32;
        wsh[rr * 257 + c] = WhD[(size_t)(third * 256 + k0 + kr) * 256 + c];
    }
    const float bhr = bh_g[d * 768 + k0 + kk2];
    const float bhz = bh_g[d * 768 + 256 + k0 + kk2];
    const float bhn = bh_g[d * 768 + 512 + k0 + kk2];
    const int flagbase = (d * 8 + sg) * 129;
    __syncthreads();

    for (int w = 0; w < 128; ++w) {
        if (w > 0) {
            if (tid == 0) {
                volatile int* fp = &g_flag[flagbase + w];
                while (*fp < 8) { __nanosleep(32); }
            }
            __syncthreads();
        }
        // Load h(w) for our 8 sentences (bypass L1 — written by other SMs)
        {
            const float4* h4 = (const float4*)(g_H + (((size_t)d * 129 + w) * 64 + s0) * 256);
            float4* hb4 = (float4*)hbuf;
            hb4[tid]       = __ldcg(h4 + tid);
            hb4[tid + 256] = __ldcg(h4 + tid + 256);
        }
        __syncthreads();

        // Partial dot products: thread (q,kk) -> rows {kk,32+kk,64+kk} x 8 sent, c-chunk q
        float acc0[8] = {}, acc1[8] = {}, acc2[8] = {};
        const float* w0p = wsh + (size_t)kk * 257;
        const float* w1p = wsh + (size_t)(32 + kk) * 257;
        const float* w2p = wsh + (size_t)(64 + kk) * 257;
        const int cbase = q * 32;
#pragma unroll 4
        for (int cc = 0; cc < 32; ++cc) {
            int c = cbase + cc;
            float w0 = w0p[c], w1 = w1p[c], w2 = w2p[c];
#pragma unroll
            for (int sl = 0; sl < 8; ++sl) {
                float h = hbuf[sl * 256 + c];
                acc0[sl] += w0 * h; acc1[sl] += w1 * h; acc2[sl] += w2 * h;
            }
        }
#pragma unroll
        for (int sl = 0; sl < 8; ++sl) {
            red[(q * 96 + kk) * 9 + sl]      = acc0[sl];
            red[(q * 96 + 32 + kk) * 9 + sl] = acc1[sl];
            red[(q * 96 + 64 + kk) * 9 + sl] = acc2[sl];
        }
        __syncthreads();

        // Final: thread (sl2, kk2) reduces 8 partials per gate, applies GRU cell
        float sr = 0.f, sz = 0.f, sn = 0.f;
#pragma unroll
        for (int qq = 0; qq < 8; ++qq) {
            sr += red[(qq * 96 + kk2) * 9 + sl2];
            sz += red[(qq * 96 + 32 + kk2) * 9 + sl2];
            sn += red[(qq * 96 + 64 + kk2) * 9 + sl2];
        }
        const float* gi = g_Gi + (((size_t)d * 128 + w) * 64 + (s0 + sl2)) * 768;
        float gir = gi[k0 + kk2];
        float giz = gi[256 + k0 + kk2];
        float gin = gi[512 + k0 + kk2];
        float r = sigf(gir + sr + bhr);
        float z = sigf(giz + sz + bhz);
        float n = tanhf(gin + r * (sn + bhn));
        float hprev = hbuf[sl2 * 256 + k0 + kk2];
        float hnew = (1.f - z) * n + z * hprev;
        __stcg(g_H + (((size_t)d * 129 + (w + 1)) * 64 + (s0 + sl2)) * 256 + k0 + kk2, hnew);
        __threadfence();
        __syncthreads();
        if (tid == 0) atomicAdd(&g_flag[flagbase + w + 1], 1);
    }
}

// ---------------------------------------------------------------------------
// K3: u_word[s][w][:] = tanh(concat(h_fwd,h_bwd) @ wa_W^T + wa_b)
// rows r = s*128 + w. grid (8, 128), 256 thr.
// ---------------------------------------------------------------------------
__global__ void __launch_bounds__(256) k3_uword(const float* __restrict__ waW,
                                                const float* __restrict__ wab) {
    __shared__ float As[16][64];
    __shared__ float Bs[16][64];
    const int j0 = blockIdx.x * 64;
    const int r0 = blockIdx.y * 64;
    const int tid = threadIdx.x;
    const int tx = tid & 15, ty = tid >> 4;
    const int li = tid >> 2;
    const int lk = (tid & 3) << 2;
    const int r_l = r0 + li;
    const int s_l = r_l >> 7;
    const int w_l = r_l & 127;
    float acc[4][4] = {};
    for (int kt = 0; kt < 512; kt += 16) {
        int kg = kt + lk;
        int dsel = kg >> 8;
        int kloc = kg & 255;
        float4 av = *(const float4*)(g_H + (((size_t)dsel * 129 + (w_l + 1)) * 64 + s_l) * 256 + kloc);
        float4 bv = *(const float4*)(waW + (size_t)(j0 + li) * 512 + kg);
        As[lk + 0][li] = av.x; As[lk + 1][li] = av.y; As[lk + 2][li] = av.z; As[lk + 3][li] = av.w;
        Bs[lk + 0][li] = bv.x; Bs[lk + 1][li] = bv.y; Bs[lk + 2][li] = bv.z; Bs[lk + 3][li] = bv.w;
        __syncthreads();
        mm16(As, Bs, tx, ty, acc);
        __syncthreads();
    }
#pragma unroll
    for (int ii = 0; ii < 4; ++ii) {
        int r = r0 + ty * 4 + ii;
#pragma unroll
        for (int jj = 0; jj < 4; ++jj) {
            int j = j0 + tx * 4 + jj;
            g_Uw[(size_t)r * 512 + j] = tanhf(acc[ii][jj] + wab[j]);
        }
    }
}

// K4: sent_summ[s][j] = sum_w u_word[s][w][j]  (word attention weights == 1)
__global__ void k4_reduce() {
    int s = blockIdx.x;
    int j = blockIdx.y * 128 + threadIdx.x;
    const float* p = g_Uw + (size_t)s * 128 * 512 + j;
    float a = 0.f;
    for (int w = 0; w < 128; ++w) a += p[w * 512];
    g_sent[s * 512 + j] = a;
}

// K5a: sentence gi[d] = sent_summ @ s_Wi[d]^T + s_bi[d].  grid (24,1,2)
__global__ void __launch_bounds__(256) k5a_sgi(const float* __restrict__ sWi,
                                               const float* __restrict__ sbi) {
    __shared__ float As[16][64];
    __shared__ float Bs[16][64];
    const int d = blockIdx.z;
    const int j0 = blockIdx.x * 64;
    const int tid = threadIdx.x;
    const int tx = tid & 15, ty = tid >> 4;
    const int li = tid >> 2;
    const int lk = (tid & 3) << 2;
    const float* B = sWi + (size_t)d * 1536 * 512;
    float acc[4][4] = {};
    for (int kt = 0; kt < 512; kt += 16) {
        float4 av = *(const float4*)(g_sent + (size_t)li * 512 + kt + lk);
        float4 bv = *(const float4*)(B + (size_t)(j0 + li) * 512 + kt + lk);
        As[lk + 0][li] = av.x; As[lk + 1][li] = av.y; As[lk + 2][li] = av.z; As[lk + 3][li] = av.w;
        Bs[lk + 0][li] = bv.x; Bs[lk + 1][li] = bv.y; Bs[lk + 2][li] = bv.z; Bs[lk + 3][li] = bv.w;
        __syncthreads();
        mm16(As, Bs, tx, ty, acc);
        __syncthreads();
    }
#pragma unroll
    for (int ii = 0; ii < 4; ++ii) {
        int s = ty * 4 + ii;
#pragma unroll
        for (int jj = 0; jj < 4; ++jj) {
            int j = j0 + tx * 4 + jj;
            g_sgi[((size_t)d * 64 + s) * 1536 + j] = acc[ii][jj] + sbi[d * 1536 + j];
        }
    }
}

// K5b: sentence GRU gate with zero hidden state: sentenc[s][d*512+j] = (1-z)*n
__global__ void k5b_gate(const float* __restrict__ sbh) {
    int idx = blockIdx.x * 256 + threadIdx.x;
    if (idx >= 2 * 64 * 512) return;
    int d = idx >> 15;
    int rem = idx & 32767;
    int s = rem >> 9;
    int j = rem & 511;
    const float* gi = g_sgi + ((size_t)d * 64 + s) * 1536;
    float gir = gi[j], giz = gi[512 + j], gin = gi[1024 + j];
    float hr = sbh[d * 1536 + j];
    float hz = sbh[d * 1536 + 512 + j];
    float hn = sbh[d * 1536 + 1024 + j];
    float r = sigf(gir + hr);
    float z = sigf(giz + hz);
    float n = tanhf(gin + r * hn);
    g_sentenc[s * 1024 + d * 512 + j] = (1.f - z) * n;
}

// K5c: u_sent = tanh(sentenc @ sa_W^T + sa_b).  grid (16,1,1)
__global__ void __launch_bounds__(256) k5c_usent(const float* __restrict__ saW,
                                                 const float* __restrict__ sab) {
    __shared__ float As[16][64];
    __shared__ float Bs[16][64];
    const int j0 = blockIdx.x * 64;
    const int tid = threadIdx.x;
    const int tx = tid & 15, ty = tid >> 4;
    const int li = tid >> 2;
    const int lk = (tid & 3) << 2;
    float acc[4][4] = {};
    for (int kt = 0; kt < 1024; kt += 16) {
        float4 av = *(const float4*)(g_sentenc + (size_t)li * 1024 + kt + lk);
        float4 bv = *(const float4*)(saW + (size_t)(j0 + li) * 1024 + kt + lk);
        As[lk + 0][li] = av.x; As[lk + 1][li] = av.y; As[lk + 2][li] = av.z; As[lk + 3][li] = av.w;
        Bs[lk + 0][li] = bv.x; Bs[lk + 1][li] = bv.y; Bs[lk + 2][li] = bv.z; Bs[lk + 3][li] = bv.w;
        __syncthreads();
        mm16(As, Bs, tx, ty, acc);
        __syncthreads();
    }
#pragma unroll
    for (int ii = 0; ii < 4; ++ii) {
        int s = ty * 4 + ii;
#pragma unroll
        for (int jj = 0; jj < 4; ++jj) {
            int j = j0 + tx * 4 + jj;
            g_usent[(size_t)s * 1024 + j] = tanhf(acc[ii][jj] + sab[j]);
        }
    }
}

// K6: doc = sum_s u_sent; logits = doc @ do_W^T + do_b; log_softmax -> last 13 outs
__global__ void k6_final(const float* __restrict__ doW, const float* __restrict__ dob,
                         float* __restrict__ out, int out_size) {
    __shared__ float doc[1024];
    __shared__ float lg[16];
    int tid = threadIdx.x;
    for (int j = tid; j < 1024; j += 256) {
        float a = 0.f;
        for (int s = 0; s < 64; ++s) a += g_usent[s * 1024 + j];
        doc[j] = a;
    }
    __syncthreads();
    int wid = tid >> 5, lane = tid & 31;
    for (int c = wid; c < 13; c += 8) {
        float p = 0.f;
        for (int k = lane; k < 1024; k += 32) p += doc[k] * doW[c * 1024 + k];
#pragma unroll
        for (int o = 16; o > 0; o >>= 1) p += __shfl_xor_sync(0xffffffffu, p, o);
        if (lane == 0) lg[c] = p + dob[c];
    }
    __syncthreads();
    if (tid == 0) {
        float m = lg[0];
        for (int c = 1; c < 13; ++c) m = fmaxf(m, lg[c]);
        float sum = 0.f;
        for (int c = 0; c < 13; ++c) sum += expf(lg[c] - m);
        float lse = m + logf(sum);
        for (int c = 0; c < 13; ++c) out[out_size - 13 + c] = lg[c] - lse;
    }
}

// ---------------------------------------------------------------------------
extern "C" void kernel_launch(void* const* d_in, const int* in_sizes, int n_in,
                              void* d_out, int out_size) {
    const int*   doc = (const int*)  d_in[0];
    const float* emb = (const float*)d_in[1];
    const float* wWi = (const float*)d_in[2];
    const float* wWh = (const float*)d_in[3];
    const float* wbi = (const float*)d_in[4];
    const float* wbh = (const float*)d_in[5];
    const float* sWi = (const float*)d_in[6];
    // d_in[7] = s_Wh: unused (sentence GRU sees zero hidden state)
    const float* sbi = (const float*)d_in[8];
    const float* sbh = (const float*)d_in[9];
    const float* waW = (const float*)d_in[10];
    const float* wab = (const float*)d_in[11];
    // d_in[12] = uw_W: unused (softmax over size-1 axis == 1)
    const float* saW = (const float*)d_in[13];
    const float* sab = (const float*)d_in[14];
    // d_in[15] = us_W: unused
    const float* doW = (const float*)d_in[16];
    const float* dob = (const float*)d_in[17];
    float* out = (float*)d_out;

    const int SMEM_K2 = (96 * 257 + 8 * 256 + 8 * 96 * 9) * 4;  // 134528 B
    cudaFuncSetAttribute(k2_rec, cudaFuncAttributeMaxDynamicSharedMemorySize, SMEM_K2);

    k0_init<<<64, 256>>>(out, out_size - 13);
    k1_gi<<<dim3(12, 128, 2), 256>>>(doc, emb, wWi, wbi);
    k2_rec<<<128, 256, SMEM_K2>>>(wWh, wbh);
    k3_uword<<<dim3(8, 128, 1), 256>>>(waW, wab);
    k4_reduce<<<dim3(64, 4), 128>>>();
    k5a_sgi<<<dim3(24, 1, 2), 256>>>(sWi, sbi);
    k5b_gate<<<256, 256>>>(sbh);
    k5c_usent<<<dim3(16, 1, 1), 256>>>(saW, sab);
    k6_final<<<1, 256>>>(doW, dob, out, out_size);
}

// round 4
// speedup vs baseline: 1.3920x; 1.3920x over previous
#include <cuda_runtime.h>
#include <math.h>
#include <stdint.h>

// S=64, W=128, D=256, HW=256, HS=512, C=13

// ---------------------------------------------------------------------------
// Scratch (static device globals — no allocation allowed)
// ---------------------------------------------------------------------------
__device__ __align__(16) float g_Gi[2u*128*64*768];   // [d][w][s][768]
__device__ __align__(16) float g_H[2u*129*64*256];    // [d][w][s][256]
__device__ __align__(16) float g_Uw[64u*128*512];     // [s][w][512]
__device__ __align__(16) float g_sent[64*512];
__device__ __align__(16) float g_sgi[2*64*1536];
__device__ __align__(16) float g_sentenc[64*1024];
__device__ __align__(16) float g_usent[64*1024];
__device__ int   g_flag[2*8*129];

__device__ __forceinline__ float sigf(float x) { return 1.f / (1.f + expf(-x)); }

__device__ __forceinline__ uint32_t f2tf(float f) {
    uint32_t u;
    asm("cvt.rna.tf32.f32 %0, %1;" : "=r"(u) : "f"(f));
    return u;
}

__device__ __forceinline__ void mma8(float c[4], const uint32_t a[4], const uint32_t b[2]) {
    asm volatile(
        "mma.sync.aligned.m16n8k8.row.col.f32.tf32.tf32.f32 "
        "{%0,%1,%2,%3}, {%4,%5,%6,%7}, {%8,%9}, {%0,%1,%2,%3};"
        : "+f"(c[0]), "+f"(c[1]), "+f"(c[2]), "+f"(c[3])
        : "r"(a[0]), "r"(a[1]), "r"(a[2]), "r"(a[3]), "r"(b[0]), "r"(b[1]));
}

// ---------------------------------------------------------------------------
// K0: init flags, h0, attention-weight outputs (exact ones)
// ---------------------------------------------------------------------------
__global__ void k0_init(float* __restrict__ out, int ones_n) {
    int i = blockIdx.x * blockDim.x + threadIdx.x;
    int stride = gridDim.x * blockDim.x;
    for (int j = i; j < 2 * 8 * 129; j += stride) g_flag[j] = 0;
    for (int j = i; j < 64 * 256; j += stride) {
        g_H[j] = 0.f;
        g_H[129u * 64 * 256 + j] = 0.f;
    }
    for (int j = i; j < ones_n; j += stride) out[j] = 1.0f;
}

// ---------------------------------------------------------------------------
// Unified tf32 tensor-core GEMM: C[M,N] = act(A[M,K] @ B[N,K]^T + bias)
// Block tile 128(M) x 64(N), 256 threads = 8 warps (2 m-groups x 4 n-groups).
// MODE 0: k1  gi   = emb[doc] @ wWi^T + wbi             (K=256, N=768, z=dir)
// MODE 1: k3  Uw   = tanh(concat(H) @ waW^T + wab)      (K=512, N=512)
// MODE 2: k5a sgi  = sent_summ @ sWi^T + sbi            (K=512, N=1536, z=dir, M=64)
// MODE 3: k5c usent= tanh(sentenc @ saW^T + sab)        (K=1024, N=1024, M=64)
// ---------------------------------------------------------------------------
template<int MODE>
__global__ void __launch_bounds__(256) gemm_tf32(const int* __restrict__ doc,
                                                 const float* __restrict__ Aext,
                                                 const float* __restrict__ Bw,
                                                 const float* __restrict__ bias) {
    constexpr int K    = (MODE == 0) ? 256 : (MODE == 3) ? 1024 : 512;
    constexpr bool TANH = (MODE == 1) || (MODE == 3);
    constexpr int MV   = (MODE >= 2) ? 64 : 128;   // valid rows

    __shared__ float As[128][36];
    __shared__ float Bs[64][36];
    __shared__ int toks[128];

    const int tid = threadIdx.x;
    const int z   = blockIdx.z;
    const int j0  = blockIdx.x * 64;
    const int r0  = blockIdx.y * 128;

    const float* B = Bw;
    const float* bi = bias;
    float* out;
    int ldC;
    if constexpr (MODE == 0) {
        B  += (size_t)z * 768 * 256;
        bi += z * 768;
        out = g_Gi + (size_t)z * 8192 * 768;
        ldC = 768;
    } else if constexpr (MODE == 1) {
        out = g_Uw; ldC = 512;
    } else if constexpr (MODE == 2) {
        B  += (size_t)z * 1536 * 512;
        bi += z * 1536;
        out = g_sgi + (size_t)z * 64 * 1536;
        ldC = 1536;
    } else {
        out = g_usent; ldC = 1024;
    }

    if constexpr (MODE == 0) {
        if (tid < 128) {
            int s = tid & 63, wl = tid >> 6;
            toks[tid] = doc[s * 128 + (r0 >> 6) + wl];
        }
        __syncthreads();
    }

    const int lane = tid & 31, wid = tid >> 5;
    const int g = lane >> 2, t = lane & 3;
    const int mbase = (wid & 1) * 64;
    const int nbase = (wid >> 1) * 16;

    float acc[4][2][4] = {};

    for (int kt = 0; kt < K; kt += 32) {
        // ---- stage A (128x32) ----
#pragma unroll
        for (int it = 0; it < 4; ++it) {
            int f = tid + it * 256;
            int row = f >> 3;
            int c4 = (f & 7) << 2;
            int kg = kt + c4;
            const float* src;
            if constexpr (MODE == 0) {
                src = Aext + (size_t)toks[row] * 256 + kg;
            } else if constexpr (MODE == 1) {
                int r = r0 + row;
                int s = r >> 7, w = r & 127;
                int dsel = kg >> 8, kl = kg & 255;
                src = g_H + (((size_t)dsel * 129 + (w + 1)) * 64 + s) * 256 + kl;
            } else if constexpr (MODE == 2) {
                int rr = row < 64 ? row : 63;
                src = g_sent + (size_t)rr * 512 + kg;
            } else {
                int rr = row < 64 ? row : 63;
                src = g_sentenc + (size_t)rr * 1024 + kg;
            }
            float4 v = *(const float4*)src;
            As[row][c4 + 0] = __uint_as_float(f2tf(v.x));
            As[row][c4 + 1] = __uint_as_float(f2tf(v.y));
            As[row][c4 + 2] = __uint_as_float(f2tf(v.z));
            As[row][c4 + 3] = __uint_as_float(f2tf(v.w));
        }
        // ---- stage B (64x32) ----
#pragma unroll
        for (int it = 0; it < 2; ++it) {
            int f = tid + it * 256;
            int row = f >> 3;
            int c4 = (f & 7) << 2;
            float4 v = *(const float4*)(B + (size_t)(j0 + row) * K + kt + c4);
            Bs[row][c4 + 0] = __uint_as_float(f2tf(v.x));
            Bs[row][c4 + 1] = __uint_as_float(f2tf(v.y));
            Bs[row][c4 + 2] = __uint_as_float(f2tf(v.z));
            Bs[row][c4 + 3] = __uint_as_float(f2tf(v.w));
        }
        __syncthreads();

#pragma unroll
        for (int kc = 0; kc < 32; kc += 8) {
            uint32_t a[4][4], b[2][2];
#pragma unroll
            for (int mt = 0; mt < 4; ++mt) {
                int rr = mbase + mt * 16 + g;
                a[mt][0] = __float_as_uint(As[rr][kc + t]);
                a[mt][1] = __float_as_uint(As[rr + 8][kc + t]);
                a[mt][2] = __float_as_uint(As[rr][kc + t + 4]);
                a[mt][3] = __float_as_uint(As[rr + 8][kc + t + 4]);
            }
#pragma unroll
            for (int nt = 0; nt < 2; ++nt) {
                int nn = nbase + nt * 8 + g;
                b[nt][0] = __float_as_uint(Bs[nn][kc + t]);
                b[nt][1] = __float_as_uint(Bs[nn][kc + t + 4]);
            }
#pragma unroll
            for (int mt = 0; mt < 4; ++mt)
#pragma unroll
                for (int nt = 0; nt < 2; ++nt)
                    mma8(acc[mt][nt], a[mt], b[nt]);
        }
        __syncthreads();
    }

    // ---- epilogue ----
#pragma unroll
    for (int mt = 0; mt < 4; ++mt) {
#pragma unroll
        for (int nt = 0; nt < 2; ++nt) {
            int col = j0 + nbase + nt * 8 + 2 * t;
            float b0 = bi[col], b1 = bi[col + 1];
            int row = mbase + mt * 16 + g;
#pragma unroll
            for (int half = 0; half < 2; ++half) {
                int r = row + half * 8;
                if (r < MV) {
                    float v0 = acc[mt][nt][half * 2 + 0] + b0;
                    float v1 = acc[mt][nt][half * 2 + 1] + b1;
                    if (TANH) { v0 = tanhf(v0); v1 = tanhf(v1); }
                    float2 st = make_float2(v0, v1);
                    *(float2*)(out + (size_t)(r0 + r) * ldC + col) = st;
                }
            }
        }
    }
}

// ---------------------------------------------------------------------------
// K2: word GRU recurrence. 128 blocks = dir(2) x ktile(8 x 32cols) x sgroup(8 x 8sent)
// Weight slice (96 x 256) in SMEM; h via L2 with release/acquire flag counters.
// ---------------------------------------------------------------------------
__global__ void __launch_bounds__(256) k2_rec(const float* __restrict__ Wh,
                                              const float* __restrict__ bh_g) {
    const int b  = blockIdx.x;
    const int d  = b >> 6;
    const int kt = (b >> 3) & 7;
    const int sg = b & 7;
    const int k0 = kt * 32;
    const int s0 = sg * 8;
    const int tid = threadIdx.x;
    const int kk  = tid & 31;
    const int q   = tid >> 5;
    const int sl2 = tid >> 5;
    const int kk2 = tid & 31;

    extern __shared__ float sm[];
    float* wsh  = sm;                    // 96 x 257
    float* hbuf = wsh + 96 * 257;        // 8 x 256
    float* red  = hbuf + 8 * 256;        // 8 x 96 x 9

    const float* WhD = Wh + (size_t)d * 768 * 256;
    for (int e = tid; e < 96 * 256; e += 256) {
        int rr = e >> 8, c = e & 255;
        int third = rr / 32, kr = rr % 32;
        wsh[rr * 257 + c] = WhD[(size_t)(third * 256 + k0 + kr) * 256 + c];
    }
    const float bhr = bh_g[d * 768 + k0 + kk2];
    const float bhz = bh_g[d * 768 + 256 + k0 + kk2];
    const float bhn = bh_g[d * 768 + 512 + k0 + kk2];
    const int flagbase = (d * 8 + sg) * 129;
    __syncthreads();

    for (int w = 0; w < 128; ++w) {
        if (w > 0) {
            if (tid == 0) {
                int v;
                do {
                    asm volatile("ld.acquire.gpu.global.s32 %0, [%1];"
                                 : "=r"(v) : "l"(&g_flag[flagbase + w]) : "memory");
                    if (v < 8) __nanosleep(20);
                } while (v < 8);
            }
            __syncthreads();
        }
        {
            const float4* h4 = (const float4*)(g_H + (((size_t)d * 129 + w) * 64 + s0) * 256);
            float4* hb4 = (float4*)hbuf;
            hb4[tid]       = __ldcg(h4 + tid);
            hb4[tid + 256] = __ldcg(h4 + tid + 256);
        }
        __syncthreads();

        float acc0[8] = {}, acc1[8] = {}, acc2[8] = {};
        const float* w0p = wsh + (size_t)kk * 257;
        const float* w1p = wsh + (size_t)(32 + kk) * 257;
        const float* w2p = wsh + (size_t)(64 + kk) * 257;
        const int cbase = q * 32;
#pragma unroll 4
        for (int cc = 0; cc < 32; ++cc) {
            int c = cbase + cc;
            float w0 = w0p[c], w1 = w1p[c], w2 = w2p[c];
#pragma unroll
            for (int sl = 0; sl < 8; ++sl) {
                float h = hbuf[sl * 256 + c];
                acc0[sl] += w0 * h; acc1[sl] += w1 * h; acc2[sl] += w2 * h;
            }
        }
#pragma unroll
        for (int sl = 0; sl < 8; ++sl) {
            red[(q * 96 + kk) * 9 + sl]      = acc0[sl];
            red[(q * 96 + 32 + kk) * 9 + sl] = acc1[sl];
            red[(q * 96 + 64 + kk) * 9 + sl] = acc2[sl];
        }
        __syncthreads();

        float sr = 0.f, sz = 0.f, sn = 0.f;
#pragma unroll
        for (int qq = 0; qq < 8; ++qq) {
            sr += red[(qq * 96 + kk2) * 9 + sl2];
            sz += red[(qq * 96 + 32 + kk2) * 9 + sl2];
            sn += red[(qq * 96 + 64 + kk2) * 9 + sl2];
        }
        const float* gi = g_Gi + (((size_t)d * 128 + w) * 64 + (s0 + sl2)) * 768;
        float gir = gi[k0 + kk2];
        float giz = gi[256 + k0 + kk2];
        float gin = gi[512 + k0 + kk2];
        float r = sigf(gir + sr + bhr);
        float z = sigf(giz + sz + bhz);
        float n = tanhf(gin + r * (sn + bhn));
        float hprev = hbuf[sl2 * 256 + k0 + kk2];
        float hnew = (1.f - z) * n + z * hprev;
        __stcg(g_H + (((size_t)d * 129 + (w + 1)) * 64 + (s0 + sl2)) * 256 + k0 + kk2, hnew);
        __syncthreads();
        if (tid == 0)
            asm volatile("red.release.gpu.global.add.s32 [%0], %1;"
                         :: "l"(&g_flag[flagbase + w + 1]), "r"(1) : "memory");
    }
}

// K4: sent_summ[s][j] = sum_w u_word[s][w][j]
__global__ void k4_reduce() {
    int s = blockIdx.x;
    int j = blockIdx.y * 128 + threadIdx.x;
    const float* p = g_Uw + (size_t)s * 128 * 512 + j;
    float a = 0.f;
    for (int w = 0; w < 128; ++w) a += p[w * 512];
    g_sent[s * 512 + j] = a;
}

// K5b: sentence GRU gate with zero hidden state
__global__ void k5b_gate(const float* __restrict__ sbh) {
    int idx = blockIdx.x * 256 + threadIdx.x;
    if (idx >= 2 * 64 * 512) return;
    int d = idx >> 15;
    int rem = idx & 32767;
    int s = rem >> 9;
    int j = rem & 511;
    const float* gi = g_sgi + ((size_t)d * 64 + s) * 1536;
    float gir = gi[j], giz = gi[512 + j], gin = gi[1024 + j];
    float hr = sbh[d * 1536 + j];
    float hz = sbh[d * 1536 + 512 + j];
    float hn = sbh[d * 1536 + 1024 + j];
    float r = sigf(gir + hr);
    float z = sigf(giz + hz);
    float n = tanhf(gin + r * hn);
    g_sentenc[s * 1024 + d * 512 + j] = (1.f - z) * n;
}

// K6: doc sum, logits, log_softmax
__global__ void k6_final(const float* __restrict__ doW, const float* __restrict__ dob,
                         float* __restrict__ out, int out_size) {
    __shared__ float doc[1024];
    __shared__ float lg[16];
    int tid = threadIdx.x;
    for (int j = tid; j < 1024; j += 256) {
        float a = 0.f;
        for (int s = 0; s < 64; ++s) a += g_usent[s * 1024 + j];
        doc[j] = a;
    }
    __syncthreads();
    int wid = tid >> 5, lane = tid & 31;
    for (int c = wid; c < 13; c += 8) {
        float p = 0.f;
        for (int k = lane; k < 1024; k += 32) p += doc[k] * doW[c * 1024 + k];
#pragma unroll
        for (int o = 16; o > 0; o >>= 1) p += __shfl_xor_sync(0xffffffffu, p, o);
        if (lane == 0) lg[c] = p + dob[c];
    }
    __syncthreads();
    if (tid == 0) {
        float m = lg[0];
        for (int c = 1; c < 13; ++c) m = fmaxf(m, lg[c]);
        float sum = 0.f;
        for (int c = 0; c < 13; ++c) sum += expf(lg[c] - m);
        float lse = m + logf(sum);
        for (int c = 0; c < 13; ++c) out[out_size - 13 + c] = lg[c] - lse;
    }
}

// ---------------------------------------------------------------------------
extern "C" void kernel_launch(void* const* d_in, const int* in_sizes, int n_in,
                              void* d_out, int out_size) {
    const int*   doc = (const int*)  d_in[0];
    const float* emb = (const float*)d_in[1];
    const float* wWi = (const float*)d_in[2];
    const float* wWh = (const float*)d_in[3];
    const float* wbi = (const float*)d_in[4];
    const float* wbh = (const float*)d_in[5];
    const float* sWi = (const float*)d_in[6];
    const float* sbi = (const float*)d_in[8];
    const float* sbh = (const float*)d_in[9];
    const float* waW = (const float*)d_in[10];
    const float* wab = (const float*)d_in[11];
    const float* saW = (const float*)d_in[13];
    const float* sab = (const float*)d_in[14];
    const float* doW = (const float*)d_in[16];
    const float* dob = (const float*)d_in[17];
    float* out = (float*)d_out;

    const int SMEM_K2 = (96 * 257 + 8 * 256 + 8 * 96 * 9) * 4;
    cudaFuncSetAttribute(k2_rec, cudaFuncAttributeMaxDynamicSharedMemorySize, SMEM_K2);

    k0_init<<<64, 256>>>(out, out_size - 13);
    gemm_tf32<0><<<dim3(12, 64, 2), 256>>>(doc, emb, wWi, wbi);
    k2_rec<<<128, 256, SMEM_K2>>>(wWh, wbh);
    gemm_tf32<1><<<dim3(8, 64, 1), 256>>>(nullptr, nullptr, waW, wab);
    k4_reduce<<<dim3(64, 4), 128>>>();
    gemm_tf32<2><<<dim3(24, 1, 2), 256>>>(nullptr, nullptr, sWi, sbi);
    k5b_gate<<<256, 256>>>(sbh);
    gemm_tf32<3><<<dim3(16, 1, 1), 256>>>(nullptr, nullptr, saW, sab);
    k6_final<<<1, 256>>>(doW, dob, out, out_size);
}

// round 5
// speedup vs baseline: 1.9552x; 1.4046x over previous
#include <cuda_runtime.h>
#include <math.h>
#include <stdint.h>

// S=64, W=128, D=256, HW=256, HS=512, C=13

// ---------------------------------------------------------------------------
// Scratch (static device globals — no allocation allowed)
// ---------------------------------------------------------------------------
__device__ __align__(16) float g_Gi[2u*128*64*768];   // [d][w][s][768]
__device__ __align__(16) float g_H[2u*129*64*256];    // [d][w][s][256]
__device__ __align__(16) float g_Uw[64u*128*512];     // [s][w][512]
__device__ __align__(16) float g_sent[64*512];
__device__ __align__(16) float g_sgi[2*64*1536];
__device__ __align__(16) float g_sentenc[64*1024];
__device__ __align__(16) float g_usent[64*1024];
__device__ int   g_flag[2*8*129];

__device__ __forceinline__ float sigf(float x) { return 1.f / (1.f + expf(-x)); }

__device__ __forceinline__ uint32_t f2tf(float f) {
    uint32_t u;
    asm("cvt.rna.tf32.f32 %0, %1;" : "=r"(u) : "f"(f));
    return u;
}

__device__ __forceinline__ void mma8(float c[4], const uint32_t a[4], const uint32_t b[2]) {
    asm volatile(
        "mma.sync.aligned.m16n8k8.row.col.f32.tf32.tf32.f32 "
        "{%0,%1,%2,%3}, {%4,%5,%6,%7}, {%8,%9}, {%0,%1,%2,%3};"
        : "+f"(c[0]), "+f"(c[1]), "+f"(c[2]), "+f"(c[3])
        : "r"(a[0]), "r"(a[1]), "r"(a[2]), "r"(a[3]), "r"(b[0]), "r"(b[1]));
}

// ---------------------------------------------------------------------------
// K0: init flags, h0, attention-weight outputs (exact ones)
// ---------------------------------------------------------------------------
__global__ void k0_init(float* __restrict__ out, int ones_n) {
    int i = blockIdx.x * blockDim.x + threadIdx.x;
    int stride = gridDim.x * blockDim.x;
    for (int j = i; j < 2 * 8 * 129; j += stride) g_flag[j] = 0;
    for (int j = i; j < 64 * 256; j += stride) {
        g_H[j] = 0.f;
        g_H[129u * 64 * 256 + j] = 0.f;
    }
    for (int j = i; j < ones_n; j += stride) out[j] = 1.0f;
}

// ---------------------------------------------------------------------------
// Unified tf32 tensor-core GEMM: C[M,N] = act(A[M,K] @ B[N,K]^T + bias)
// (unchanged from R4 — see modes in comments)
// ---------------------------------------------------------------------------
template<int MODE>
__global__ void __launch_bounds__(256) gemm_tf32(const int* __restrict__ doc,
                                                 const float* __restrict__ Aext,
                                                 const float* __restrict__ Bw,
                                                 const float* __restrict__ bias) {
    constexpr int K    = (MODE == 0) ? 256 : (MODE == 3) ? 1024 : 512;
    constexpr bool TANH = (MODE == 1) || (MODE == 3);
    constexpr int MV   = (MODE >= 2) ? 64 : 128;   // valid rows

    __shared__ float As[128][36];
    __shared__ float Bs[64][36];
    __shared__ int toks[128];

    const int tid = threadIdx.x;
    const int z   = blockIdx.z;
    const int j0  = blockIdx.x * 64;
    const int r0  = blockIdx.y * 128;

    const float* B = Bw;
    const float* bi = bias;
    float* out;
    int ldC;
    if constexpr (MODE == 0) {
        B  += (size_t)z * 768 * 256;
        bi += z * 768;
        out = g_Gi + (size_t)z * 8192 * 768;
        ldC = 768;
    } else if constexpr (MODE == 1) {
        out = g_Uw; ldC = 512;
    } else if constexpr (MODE == 2) {
        B  += (size_t)z * 1536 * 512;
        bi += z * 1536;
        out = g_sgi + (size_t)z * 64 * 1536;
        ldC = 1536;
    } else {
        out = g_usent; ldC = 1024;
    }

    if constexpr (MODE == 0) {
        if (tid < 128) {
            int s = tid & 63, wl = tid >> 6;
            toks[tid] = doc[s * 128 + (r0 >> 6) + wl];
        }
        __syncthreads();
    }

    const int lane = tid & 31, wid = tid >> 5;
    const int g = lane >> 2, t = lane & 3;
    const int mbase = (wid & 1) * 64;
    const int nbase = (wid >> 1) * 16;

    float acc[4][2][4] = {};

    for (int kt = 0; kt < K; kt += 32) {
#pragma unroll
        for (int it = 0; it < 4; ++it) {
            int f = tid + it * 256;
            int row = f >> 3;
            int c4 = (f & 7) << 2;
            int kg = kt + c4;
            const float* src;
            if constexpr (MODE == 0) {
                src = Aext + (size_t)toks[row] * 256 + kg;
            } else if constexpr (MODE == 1) {
                int r = r0 + row;
                int s = r >> 7, w = r & 127;
                int dsel = kg >> 8, kl = kg & 255;
                src = g_H + (((size_t)dsel * 129 + (w + 1)) * 64 + s) * 256 + kl;
            } else if constexpr (MODE == 2) {
                int rr = row < 64 ? row : 63;
                src = g_sent + (size_t)rr * 512 + kg;
            } else {
                int rr = row < 64 ? row : 63;
                src = g_sentenc + (size_t)rr * 1024 + kg;
            }
            float4 v = *(const float4*)src;
            As[row][c4 + 0] = __uint_as_float(f2tf(v.x));
            As[row][c4 + 1] = __uint_as_float(f2tf(v.y));
            As[row][c4 + 2] = __uint_as_float(f2tf(v.z));
            As[row][c4 + 3] = __uint_as_float(f2tf(v.w));
        }
#pragma unroll
        for (int it = 0; it < 2; ++it) {
            int f = tid + it * 256;
            int row = f >> 3;
            int c4 = (f & 7) << 2;
            float4 v = *(const float4*)(B + (size_t)(j0 + row) * K + kt + c4);
            Bs[row][c4 + 0] = __uint_as_float(f2tf(v.x));
            Bs[row][c4 + 1] = __uint_as_float(f2tf(v.y));
            Bs[row][c4 + 2] = __uint_as_float(f2tf(v.z));
            Bs[row][c4 + 3] = __uint_as_float(f2tf(v.w));
        }
        __syncthreads();

#pragma unroll
        for (int kc = 0; kc < 32; kc += 8) {
            uint32_t a[4][4], b[2][2];
#pragma unroll
            for (int mt = 0; mt < 4; ++mt) {
                int rr = mbase + mt * 16 + g;
                a[mt][0] = __float_as_uint(As[rr][kc + t]);
                a[mt][1] = __float_as_uint(As[rr + 8][kc + t]);
                a[mt][2] = __float_as_uint(As[rr][kc + t + 4]);
                a[mt][3] = __float_as_uint(As[rr + 8][kc + t + 4]);
            }
#pragma unroll
            for (int nt = 0; nt < 2; ++nt) {
                int nn = nbase + nt * 8 + g;
                b[nt][0] = __float_as_uint(Bs[nn][kc + t]);
                b[nt][1] = __float_as_uint(Bs[nn][kc + t + 4]);
            }
#pragma unroll
            for (int mt = 0; mt < 4; ++mt)
#pragma unroll
                for (int nt = 0; nt < 2; ++nt)
                    mma8(acc[mt][nt], a[mt], b[nt]);
        }
        __syncthreads();
    }

#pragma unroll
    for (int mt = 0; mt < 4; ++mt) {
#pragma unroll
        for (int nt = 0; nt < 2; ++nt) {
            int col = j0 + nbase + nt * 8 + 2 * t;
            float b0 = bi[col], b1 = bi[col + 1];
            int row = mbase + mt * 16 + g;
#pragma unroll
            for (int half = 0; half < 2; ++half) {
                int r = row + half * 8;
                if (r < MV) {
                    float v0 = acc[mt][nt][half * 2 + 0] + b0;
                    float v1 = acc[mt][nt][half * 2 + 1] + b1;
                    if (TANH) { v0 = tanhf(v0); v1 = tanhf(v1); }
                    float2 st = make_float2(v0, v1);
                    *(float2*)(out + (size_t)(r0 + r) * ldC + col) = st;
                }
            }
        }
    }
}

// ---------------------------------------------------------------------------
// K2: word GRU recurrence — TENSOR-CORE version.
// 128 blocks = dir(2) x ktile(8 x 32 h-cols) x sgroup(8 x 8 sentences).
// 384 threads = 12 warps = 6 m-tiles(16 rows) x 2 k-halves(128).
// Per step: gh[96,8] = Wslice[96,256] @ h[8,256]^T via tf32 mma.m16n8k8.
// Weight A-fragments preloaded into registers ONCE (loop-invariant).
// h exchange via L2 + release/acquire flag counters (proven scheme).
// ---------------------------------------------------------------------------
__global__ void __launch_bounds__(384, 1) k2_rec(const float* __restrict__ Wh,
                                                 const float* __restrict__ bh_g) {
    const int b  = blockIdx.x;
    const int d  = b >> 6;
    const int kt = (b >> 3) & 7;
    const int sg = b & 7;
    const int k0 = kt * 32;
    const int s0 = sg * 8;
    const int tid  = threadIdx.x;
    const int lane = tid & 31;
    const int wu   = tid >> 5;       // 0..11
    const int mu   = wu % 6;         // m-tile (rows mu*16 .. +15 of 96)
    const int kh   = wu / 6;         // k-half (0:[0,128) 1:[128,256))
    const int g    = lane >> 2;      // 0..7
    const int t    = lane & 3;       // 0..3

    extern __shared__ float sm[];
    float* ws   = sm;                 // [96][260] weight staging (init only)
    float* hbuf = sm + 96 * 260;      // [8][264]  h(w) fp32
    float* gh   = hbuf + 8 * 264;     // [2][8][100] per-k-half partials

    // ---- init: stage weight slice, preload A fragments into registers ----
    const float* WhD = Wh + (size_t)d * 768 * 256;
    for (int e = tid; e < 96 * 256; e += 384) {
        int rr = e >> 8, c = e & 255;
        int third = rr / 32, kr = rr % 32;
        ws[rr * 260 + c] = WhD[(size_t)(third * 256 + k0 + kr) * 256 + c];
    }
    __syncthreads();

    uint32_t afr[16][4];
    {
        const int row0 = mu * 16 + g;
#pragma unroll
        for (int ks = 0; ks < 16; ++ks) {
            int kc = kh * 128 + ks * 8;
            afr[ks][0] = f2tf(ws[row0 * 260 + kc + t]);
            afr[ks][1] = f2tf(ws[(row0 + 8) * 260 + kc + t]);
            afr[ks][2] = f2tf(ws[row0 * 260 + kc + t + 4]);
            afr[ks][3] = f2tf(ws[(row0 + 8) * 260 + kc + t + 4]);
        }
    }

    // epilogue thread mapping + biases (tid < 256: sl = sentence, kk = h-col)
    const int sl = tid >> 5;         // valid for tid<256: 0..7
    const int kk = tid & 31;
    float bhr = 0.f, bhz = 0.f, bhn = 0.f;
    if (tid < 256) {
        bhr = bh_g[d * 768 + k0 + kk];
        bhz = bh_g[d * 768 + 256 + k0 + kk];
        bhn = bh_g[d * 768 + 512 + k0 + kk];
    }
    const int flagbase = (d * 8 + sg) * 129;
    __syncthreads();

    for (int w = 0; w < 128; ++w) {
        // prefetch gi (independent of flag) — hidden under flag wait + mma
        float gir = 0.f, giz = 0.f, gin = 0.f;
        if (tid < 256) {
            const float* gi = g_Gi + (((size_t)d * 128 + w) * 64 + (s0 + sl)) * 768;
            gir = gi[k0 + kk];
            giz = gi[256 + k0 + kk];
            gin = gi[512 + k0 + kk];
        }

        if (w > 0) {
            if (tid == 0) {
                int v;
                do {
                    asm volatile("ld.acquire.gpu.global.s32 %0, [%1];"
                                 : "=r"(v) : "l"(&g_flag[flagbase + w]) : "memory");
                    if (v < 8) __nanosleep(20);
                } while (v < 8);
            }
            __syncthreads();
        }

        // load h(w)[8][256] into hbuf (bypass L1 — written by other SMs)
        {
            const float* hsrc = g_H + (((size_t)d * 129 + w) * 64 + s0) * 256;
#pragma unroll
            for (int it = 0; it < 2; ++it) {
                int idx = tid + it * 384;
                if (idx < 512) {
                    int sent = idx >> 6, c4 = idx & 63;
                    float4 v = __ldcg((const float4*)(hsrc + sent * 256 + c4 * 4));
                    *(float4*)(hbuf + sent * 264 + c4 * 4) = v;
                }
            }
        }
        __syncthreads();

        // mma: c[16 rows x 8 sent] per warp, K over this warp's 128-half
        float c[4] = {0.f, 0.f, 0.f, 0.f};
#pragma unroll
        for (int ks = 0; ks < 16; ++ks) {
            int kc = kh * 128 + ks * 8;
            uint32_t bfr[2];
            bfr[0] = f2tf(hbuf[g * 264 + kc + t]);
            bfr[1] = f2tf(hbuf[g * 264 + kc + t + 4]);
            mma8(c, afr[ks], bfr);
        }
        // dump partials: gh[kh][sent][row] (row-major rows conflict-free)
        {
            float* base = gh + kh * 800;
            int r0w = mu * 16 + g;
            base[(2 * t) * 100 + r0w]         = c[0];
            base[(2 * t + 1) * 100 + r0w]     = c[1];
            base[(2 * t) * 100 + r0w + 8]     = c[2];
            base[(2 * t + 1) * 100 + r0w + 8] = c[3];
        }
        __syncthreads();

        // GRU cell: 256 threads, one (sentence, h-col) each
        if (tid < 256) {
            float sr = gh[sl * 100 + kk]       + gh[800 + sl * 100 + kk];
            float sz = gh[sl * 100 + 32 + kk]  + gh[800 + sl * 100 + 32 + kk];
            float sn = gh[sl * 100 + 64 + kk]  + gh[800 + sl * 100 + 64 + kk];
            float r = sigf(gir + sr + bhr);
            float z = sigf(giz + sz + bhz);
            float n = tanhf(gin + r * (sn + bhn));
            float hprev = hbuf[sl * 264 + k0 + kk];
            float hnew = (1.f - z) * n + z * hprev;
            __stcg(g_H + (((size_t)d * 129 + (w + 1)) * 64 + (s0 + sl)) * 256 + k0 + kk, hnew);
        }
        __syncthreads();
        if (tid == 0)
            asm volatile("red.release.gpu.global.add.s32 [%0], %1;"
                         :: "l"(&g_flag[flagbase + w + 1]), "r"(1) : "memory");
    }
}

// K4: sent_summ[s][j] = sum_w u_word[s][w][j]
__global__ void k4_reduce() {
    int s = blockIdx.x;
    int j = blockIdx.y * 128 + threadIdx.x;
    const float* p = g_Uw + (size_t)s * 128 * 512 + j;
    float a = 0.f;
    for (int w = 0; w < 128; ++w) a += p[w * 512];
    g_sent[s * 512 + j] = a;
}

// K5b: sentence GRU gate with zero hidden state
__global__ void k5b_gate(const float* __restrict__ sbh) {
    int idx = blockIdx.x * 256 + threadIdx.x;
    if (idx >= 2 * 64 * 512) return;
    int d = idx >> 15;
    int rem = idx & 32767;
    int s = rem >> 9;
    int j = rem & 511;
    const float* gi = g_sgi + ((size_t)d * 64 + s) * 1536;
    float gir = gi[j], giz = gi[512 + j], gin = gi[1024 + j];
    float hr = sbh[d * 1536 + j];
    float hz = sbh[d * 1536 + 512 + j];
    float hn = sbh[d * 1536 + 1024 + j];
    float r = sigf(gir + hr);
    float z = sigf(giz + hz);
    float n = tanhf(gin + r * hn);
    g_sentenc[s * 1024 + d * 512 + j] = (1.f - z) * n;
}

// K6: doc sum, logits, log_softmax
__global__ void k6_final(const float* __restrict__ doW, const float* __restrict__ dob,
                         float* __restrict__ out, int out_size) {
    __shared__ float doc[1024];
    __shared__ float lg[16];
    int tid = threadIdx.x;
    for (int j = tid; j < 1024; j += 256) {
        float a = 0.f;
        for (int s = 0; s < 64; ++s) a += g_usent[s * 1024 + j];
        doc[j] = a;
    }
    __syncthreads();
    int wid = tid >> 5, lane = tid & 31;
    for (int c = wid; c < 13; c += 8) {
        float p = 0.f;
        for (int k = lane; k < 1024; k += 32) p += doc[k] * doW[c * 1024 + k];
#pragma unroll
        for (int o = 16; o > 0; o >>= 1) p += __shfl_xor_sync(0xffffffffu, p, o);
        if (lane == 0) lg[c] = p + dob[c];
    }
    __syncthreads();
    if (tid == 0) {
        float m = lg[0];
        for (int c = 1; c < 13; ++c) m = fmaxf(m, lg[c]);
        float sum = 0.f;
        for (int c = 0; c < 13; ++c) sum += expf(lg[c] - m);
        float lse = m + logf(sum);
        for (int c = 0; c < 13; ++c) out[out_size - 13 + c] = lg[c] - lse;
    }
}

// ---------------------------------------------------------------------------
extern "C" void kernel_launch(void* const* d_in, const int* in_sizes, int n_in,
                              void* d_out, int out_size) {
    const int*   doc = (const int*)  d_in[0];
    const float* emb = (const float*)d_in[1];
    const float* wWi = (const float*)d_in[2];
    const float* wWh = (const float*)d_in[3];
    const float* wbi = (const float*)d_in[4];
    const float* wbh = (const float*)d_in[5];
    const float* sWi = (const float*)d_in[6];
    const float* sbi = (const float*)d_in[8];
    const float* sbh = (const float*)d_in[9];
    const float* waW = (const float*)d_in[10];
    const float* wab = (const float*)d_in[11];
    const float* saW = (const float*)d_in[13];
    const float* sab = (const float*)d_in[14];
    const float* doW = (const float*)d_in[16];
    const float* dob = (const float*)d_in[17];
    float* out = (float*)d_out;

    // smem: ws 96*260 + hbuf 8*264 + gh 2*8*100 floats
    const int SMEM_K2 = (96 * 260 + 8 * 264 + 2 * 8 * 100) * 4;  // 114,688 B
    cudaFuncSetAttribute(k2_rec, cudaFuncAttributeMaxDynamicSharedMemorySize, SMEM_K2);

    k0_init<<<64, 256>>>(out, out_size - 13);
    gemm_tf32<0><<<dim3(12, 64, 2), 256>>>(doc, emb, wWi, wbi);
    k2_rec<<<128, 384, SMEM_K2>>>(wWh, wbh);
    gemm_tf32<1><<<dim3(8, 64, 1), 256>>>(nullptr, nullptr, waW, wab);
    k4_reduce<<<dim3(64, 4), 128>>>();
    gemm_tf32<2><<<dim3(24, 1, 2), 256>>>(nullptr, nullptr, sWi, sbi);
    k5b_gate<<<256, 256>>>(sbh);
    gemm_tf32<3><<<dim3(16, 1, 1), 256>>>(nullptr, nullptr, saW, sab);
    k6_final<<<1, 256>>>(doW, dob, out, out_size);
}